// round 9
// baseline (speedup 1.0000x reference)
#include <cuda_runtime.h>
#include <cuda_fp16.h>
#include <cstdint>
#include <math.h>

// gates[4096,4096] = [x|h0] @ [w_ih|w_hh]^T, then LSTM nonlinearity.
constexpr int Bsz  = 4096;
constexpr int Hsz  = 1024;
constexpr int KTOT = 2048;

// CTA 128x128 (8 warps, warp tile 64x32), BK=64, 3-stage cp.async.
constexpr int BM = 128;
constexpr int BK = 64;
constexpr int NSTAGE = 3;
constexpr int LDA = 72;          // halves; 144B rows, ldmatrix conflict-free
constexpr int LDG = 132;         // epilogue gate-tile stride (floats)

constexpr int STAGE_HALVES = BM * LDA;                       // 9216 per matrix
constexpr int STAGE_BYTES  = 2 * STAGE_HALVES * 2;           // 36864 (A+B)
constexpr int SMEM_BYTES   = NSTAGE * STAGE_BYTES;           // 110592

__device__ __half g_Afp16[(size_t)Bsz * KTOT];
__device__ __half g_Wfp16[(size_t)(4 * Hsz) * KTOT];

// ── convert kernel: fuse + downconvert to fp16 ──────────────────────────────
__global__ void __launch_bounds__(256)
convert_kernel(const float* __restrict__ x,
               const float* __restrict__ h0,
               const float* __restrict__ w_ih,
               const float* __restrict__ w_hh)
{
    const size_t t = (size_t)blockIdx.x * 256 + threadIdx.x;
    const size_t row = t >> 8;
    const size_t ck  = (t & 255) * 8;

    const float* asrc = (ck < 1024) ? (x    + ck) : (h0   + ck - 1024);
    const float* wsrc = (ck < 1024) ? (w_ih + ck) : (w_hh + ck - 1024);

    float4 a0 = *reinterpret_cast<const float4*>(asrc + row * 1024);
    float4 a1 = *reinterpret_cast<const float4*>(asrc + row * 1024 + 4);
    float4 w0 = *reinterpret_cast<const float4*>(wsrc + row * 1024);
    float4 w1 = *reinterpret_cast<const float4*>(wsrc + row * 1024 + 4);

    __half2 ha[4] = {
        __float22half2_rn(make_float2(a0.x, a0.y)),
        __float22half2_rn(make_float2(a0.z, a0.w)),
        __float22half2_rn(make_float2(a1.x, a1.y)),
        __float22half2_rn(make_float2(a1.z, a1.w))};
    __half2 hw[4] = {
        __float22half2_rn(make_float2(w0.x, w0.y)),
        __float22half2_rn(make_float2(w0.z, w0.w)),
        __float22half2_rn(make_float2(w1.x, w1.y)),
        __float22half2_rn(make_float2(w1.z, w1.w))};

    *reinterpret_cast<uint4*>(&g_Afp16[row * KTOT + ck]) = *reinterpret_cast<uint4*>(ha);
    *reinterpret_cast<uint4*>(&g_Wfp16[row * KTOT + ck]) = *reinterpret_cast<uint4*>(hw);
}

__device__ __forceinline__ void cp16(uint32_t s, const void* g) {
    asm volatile("cp.async.cg.shared.global [%0], [%1], 16;"
                 :: "r"(s), "l"(g) : "memory");
}

__device__ __forceinline__ void ldsm4(uint32_t& r0, uint32_t& r1,
                                      uint32_t& r2, uint32_t& r3, uint32_t addr) {
    asm volatile("ldmatrix.sync.aligned.m8n8.x4.shared.b16 {%0,%1,%2,%3}, [%4];"
                 : "=r"(r0), "=r"(r1), "=r"(r2), "=r"(r3) : "r"(addr));
}

__device__ __forceinline__ void mma16816(float* d, const uint32_t* a,
                                         uint32_t b0, uint32_t b1) {
    asm volatile(
        "mma.sync.aligned.m16n8k16.row.col.f32.f16.f16.f32 "
        "{%0,%1,%2,%3},{%4,%5,%6,%7},{%8,%9},{%0,%1,%2,%3};"
        : "+f"(d[0]), "+f"(d[1]), "+f"(d[2]), "+f"(d[3])
        : "r"(a[0]), "r"(a[1]), "r"(a[2]), "r"(a[3]), "r"(b0), "r"(b1));
}

// ── fused GEMM + LSTM: 8 warps, 64x32 warp tile, double-buffered ldmatrix ───
__global__ void __launch_bounds__(256, 2)
lstm_fp16_kernel(const float* __restrict__ c0,
                 const float* __restrict__ b_ih,
                 const float* __restrict__ b_hh,
                 float* __restrict__ out)
{
    extern __shared__ __align__(16) char smraw[];
    const uint32_t smb = (uint32_t)__cvta_generic_to_shared(smraw);

    const int jt   = blockIdx.x;     // 32 hidden cols
    const int mt   = blockIdx.y;     // 128 batch rows
    const int tid  = threadIdx.x;
    const int warp = tid >> 5;
    const int lane = tid & 31;
    const int wm   = warp >> 2;      // 0..1 -> 64 M rows
    const int wn   = warp & 3;       // 0..3 -> gate (32 N cols)
    const int aRow0 = mt * BM;

    // per-lane ldmatrix byte offsets (within A / B region of a stage)
    uint32_t aoff[4], boff[2];
    {
        const int lr = lane & 15;            // row within 16-row block
        const int kc = (lane >> 4) << 3;     // 0 or 8 halves
        #pragma unroll
        for (int im = 0; im < 4; im++)
            aoff[im] = (uint32_t)(((wm * 64 + im * 16 + lr) * LDA + kc) * 2);
        #pragma unroll
        for (int p = 0; p < 2; p++)
            boff[p]  = (uint32_t)(((wn * 32 + p * 16 + lr) * LDA + kc) * 2);
    }

    float acc[4][4][4];   // [im][n8 frag][reg]
    #pragma unroll
    for (int im = 0; im < 4; im++)
        #pragma unroll
        for (int in = 0; in < 4; in++)
            #pragma unroll
            for (int e = 0; e < 4; e++) acc[im][in][e] = 0.0f;

    // stage loaders (256 threads; 4 cp.async each per matrix)
    auto issueA = [&](int it, int s) {
        const size_t kb = (size_t)it * BK;
        const uint32_t sA = smb + (uint32_t)s * STAGE_BYTES;
        #pragma unroll
        for (int i = 0; i < 4; i++) {
            int q = tid + i * 256, r = q >> 3, c4 = q & 7;
            cp16(sA + (uint32_t)((r * LDA + c4 * 8) * 2),
                 &g_Afp16[(size_t)(aRow0 + r) * KTOT + kb + c4 * 8]);
        }
    };
    auto issueB = [&](int it, int s) {
        const size_t kb = (size_t)it * BK;
        const uint32_t sB = smb + (uint32_t)s * STAGE_BYTES + STAGE_HALVES * 2;
        #pragma unroll
        for (int i = 0; i < 4; i++) {
            int q = tid + i * 256, r = q >> 3, c4 = q & 7;
            int grow = (r >> 5) * Hsz + jt * 32 + (r & 31);
            cp16(sB + (uint32_t)((r * LDA + c4 * 8) * 2),
                 &g_Wfp16[(size_t)grow * KTOT + kb + c4 * 8]);
        }
        asm volatile("cp.async.commit_group;" ::: "memory");
    };

    constexpr int NIT = KTOT / BK;   // 32
    issueA(0, 0); issueB(0, 0);
    issueA(1, 1); issueB(1, 1);

    uint32_t Af[2][4][4];   // [buf][im][reg]
    uint32_t Bf[2][2][4];   // [buf][n16-pair p][reg]; n8-frag 2p={r0,r2}, 2p+1={r1,r3}

    for (int it = 0; it < NIT; ++it) {
        if (it == NIT - 1)
            asm volatile("cp.async.wait_group 0;" ::: "memory");
        else
            asm volatile("cp.async.wait_group 1;" ::: "memory");
        __syncthreads();

        const uint32_t sA = smb + (uint32_t)(it % NSTAGE) * STAGE_BYTES;
        const uint32_t sB = sA + STAGE_HALVES * 2;

        // preload k-group 0 into buf 0
        #pragma unroll
        for (int im = 0; im < 4; im++)
            ldsm4(Af[0][im][0], Af[0][im][1], Af[0][im][2], Af[0][im][3],
                  sA + aoff[im]);
        #pragma unroll
        for (int p = 0; p < 2; p++)
            ldsm4(Bf[0][p][0], Bf[0][p][1], Bf[0][p][2], Bf[0][p][3],
                  sB + boff[p]);

        #pragma unroll
        for (int g = 0; g < 4; g++) {
            const int cur = g & 1, nxt = cur ^ 1;
            if (g < 3) {   // next group's ldmatrix BEFORE this group's mma
                const uint32_t ko = (uint32_t)((g + 1) * 32);   // 16 halves
                #pragma unroll
                for (int im = 0; im < 4; im++)
                    ldsm4(Af[nxt][im][0], Af[nxt][im][1], Af[nxt][im][2], Af[nxt][im][3],
                          sA + aoff[im] + ko);
                #pragma unroll
                for (int p = 0; p < 2; p++)
                    ldsm4(Bf[nxt][p][0], Bf[nxt][p][1], Bf[nxt][p][2], Bf[nxt][p][3],
                          sB + boff[p] + ko);
            }
            if (g == 0 && it + 2 < NIT) issueA(it + 2, (it + 2) % NSTAGE);
            if (g == 1 && it + 2 < NIT) issueB(it + 2, (it + 2) % NSTAGE);

            #pragma unroll
            for (int im = 0; im < 4; im++)
                #pragma unroll
                for (int p = 0; p < 2; p++) {
                    mma16816(acc[im][2 * p],     Af[cur][im], Bf[cur][p][0], Bf[cur][p][2]);
                    mma16816(acc[im][2 * p + 1], Af[cur][im], Bf[cur][p][1], Bf[cur][p][3]);
                }
        }
    }
    __syncthreads();   // all warps done reading smem before G overwrite

    // ── epilogue: write gate tile to smem, apply LSTM nonlinearity ──
    float* G = reinterpret_cast<float*>(smraw);   // [BM][LDG]
    {
        const int r0 = lane >> 2;
        const int cc = (lane & 3) * 2;
        #pragma unroll
        for (int im = 0; im < 4; im++)
            #pragma unroll
            for (int in = 0; in < 4; in++) {
                const int gr = wm * 64 + im * 16 + r0;
                const int gc = wn * 32 + in * 8 + cc;
                G[gr * LDG + gc]           = acc[im][in][0];
                G[gr * LDG + gc + 1]       = acc[im][in][1];
                G[(gr + 8) * LDG + gc]     = acc[im][in][2];
                G[(gr + 8) * LDG + gc + 1] = acc[im][in][3];
            }
    }
    __syncthreads();

    for (int idx = tid; idx < BM * 32; idx += 256) {
        int m  = idx >> 5;
        int j  = idx & 31;
        int row = mt * BM + m;
        int jg  = jt * 32 + j;

        float gi = G[m * LDG +      j] + b_ih[0 * Hsz + jg] + b_hh[0 * Hsz + jg];
        float gf = G[m * LDG + 32 + j] + b_ih[1 * Hsz + jg] + b_hh[1 * Hsz + jg];
        float gg = G[m * LDG + 64 + j] + b_ih[2 * Hsz + jg] + b_hh[2 * Hsz + jg];
        float go = G[m * LDG + 96 + j] + b_ih[3 * Hsz + jg] + b_hh[3 * Hsz + jg];

        float si = 1.0f / (1.0f + __expf(-gi));
        float sf = 1.0f / (1.0f + __expf(-gf));
        float so = 1.0f / (1.0f + __expf(-go));
        float tg = tanhf(gg);

        float cold = c0[(size_t)row * Hsz + jg];
        float cn = sf * cold + si * tg;
        float hn = so * tanhf(cn);

        out[(size_t)row * Hsz + jg]                     = hn;
        out[(size_t)Bsz * Hsz + (size_t)row * Hsz + jg] = cn;
    }
}

extern "C" void kernel_launch(void* const* d_in, const int* in_sizes, int n_in,
                              void* d_out, int out_size) {
    const float* x    = (const float*)d_in[0];
    const float* h0   = (const float*)d_in[1];
    const float* c0   = (const float*)d_in[2];
    const float* w_ih = (const float*)d_in[3];
    const float* w_hh = (const float*)d_in[4];
    const float* b_ih = (const float*)d_in[5];
    const float* b_hh = (const float*)d_in[6];
    float* out = (float*)d_out;

    cudaFuncSetAttribute(lstm_fp16_kernel,
                         cudaFuncAttributeMaxDynamicSharedMemorySize, SMEM_BYTES);

    convert_kernel<<<4096, 256>>>(x, h0, w_ih, w_hh);

    dim3 grid(Hsz / 32, Bsz / BM);   // (32, 32)
    lstm_fp16_kernel<<<grid, 256, SMEM_BYTES>>>(c0, b_ih, b_hh, out);
}

// round 10
// speedup vs baseline: 1.4186x; 1.4186x over previous
#include <cuda_runtime.h>
#include <cuda_fp16.h>
#include <cstdint>
#include <mma.h>
#include <math.h>

using namespace nvcuda;

// gates[4096,4096] = [x|h0] @ [w_ih|w_hh]^T, then LSTM nonlinearity.
constexpr int Bsz  = 4096;
constexpr int Hsz  = 1024;
constexpr int KTOT = 2048;

// CTA 128x128 (8 warps, warp tile 64x32 wmma), BK=64, 3-stage cp.async.
constexpr int BM = 128;
constexpr int BK = 64;
constexpr int NSTAGE = 3;
constexpr int LDA = 72;          // halves; 144B rows, LDSM conflict-free
constexpr int LDG = 132;         // epilogue gate-tile stride (floats)

constexpr int STAGE_HALVES = BM * LDA;                       // 9216 per matrix
constexpr int STAGE_BYTES  = 2 * STAGE_HALVES * 2;           // 36864 (A+B)
constexpr int SMEM_BYTES   = NSTAGE * STAGE_BYTES;           // 110592

__device__ __half g_Afp16[(size_t)Bsz * KTOT];
__device__ __half g_Wfp16[(size_t)(4 * Hsz) * KTOT];

// ── convert kernel: fuse + downconvert to fp16 ──────────────────────────────
__global__ void __launch_bounds__(256)
convert_kernel(const float* __restrict__ x,
               const float* __restrict__ h0,
               const float* __restrict__ w_ih,
               const float* __restrict__ w_hh)
{
    const size_t t = (size_t)blockIdx.x * 256 + threadIdx.x;
    const size_t row = t >> 8;
    const size_t ck  = (t & 255) * 8;

    const float* asrc = (ck < 1024) ? (x    + ck) : (h0   + ck - 1024);
    const float* wsrc = (ck < 1024) ? (w_ih + ck) : (w_hh + ck - 1024);

    float4 a0 = *reinterpret_cast<const float4*>(asrc + row * 1024);
    float4 a1 = *reinterpret_cast<const float4*>(asrc + row * 1024 + 4);
    float4 w0 = *reinterpret_cast<const float4*>(wsrc + row * 1024);
    float4 w1 = *reinterpret_cast<const float4*>(wsrc + row * 1024 + 4);

    __half2 ha[4] = {
        __float22half2_rn(make_float2(a0.x, a0.y)),
        __float22half2_rn(make_float2(a0.z, a0.w)),
        __float22half2_rn(make_float2(a1.x, a1.y)),
        __float22half2_rn(make_float2(a1.z, a1.w))};
    __half2 hw[4] = {
        __float22half2_rn(make_float2(w0.x, w0.y)),
        __float22half2_rn(make_float2(w0.z, w0.w)),
        __float22half2_rn(make_float2(w1.x, w1.y)),
        __float22half2_rn(make_float2(w1.z, w1.w))};

    *reinterpret_cast<uint4*>(&g_Afp16[row * KTOT + ck]) = *reinterpret_cast<uint4*>(ha);
    *reinterpret_cast<uint4*>(&g_Wfp16[row * KTOT + ck]) = *reinterpret_cast<uint4*>(hw);
}

__device__ __forceinline__ void cp16(void* s, const void* g) {
    unsigned int sa = (unsigned int)__cvta_generic_to_shared(s);
    asm volatile("cp.async.cg.shared.global [%0], [%1], 16;"
                 :: "r"(sa), "l"(g) : "memory");
}

// ── fused GEMM + LSTM kernel ────────────────────────────────────────────────
__global__ void __launch_bounds__(256, 2)
lstm_fp16_kernel(const float* __restrict__ c0,
                 const float* __restrict__ b_ih,
                 const float* __restrict__ b_hh,
                 float* __restrict__ out)
{
    extern __shared__ __align__(16) char smraw[];
    __half* const sm0 = reinterpret_cast<__half*>(smraw);

    const int jt  = blockIdx.x;      // 32 hidden cols per CTA
    const int mt  = blockIdx.y;      // 128 batch rows per CTA
    const int tid = threadIdx.x;
    const int warp = tid >> 5;
    const int wm = warp >> 2;        // 0..1 -> 64 M rows
    const int wn = warp & 3;         // 0..3 -> gate, 32 N cols

    const int aRow0 = mt * BM;

    wmma::fragment<wmma::accumulator, 16, 16, 16, float> c_frag[4][2];
    #pragma unroll
    for (int a = 0; a < 4; a++)
        #pragma unroll
        for (int b = 0; b < 2; b++)
            wmma::fill_fragment(c_frag[a][b], 0.0f);

    // stage loaders: A and B separately (split across kk blocks); commit in B
    auto issueA = [&](int it, int s) {
        const size_t kb = (size_t)it * BK;
        __half* sA = sm0 + (size_t)s * 2 * STAGE_HALVES;
        #pragma unroll
        for (int i = 0; i < 4; i++) {
            int q  = tid + i * 256;        // 0..1023 16B-slots
            int r  = q >> 3;               // row 0..127
            int c4 = q & 7;                // 16B col 0..7
            cp16(&sA[r * LDA + c4 * 8],
                 &g_Afp16[(size_t)(aRow0 + r) * KTOT + kb + c4 * 8]);
        }
    };
    auto issueB = [&](int it, int s) {
        const size_t kb = (size_t)it * BK;
        __half* sB = sm0 + (size_t)s * 2 * STAGE_HALVES + STAGE_HALVES;
        #pragma unroll
        for (int i = 0; i < 4; i++) {
            int q  = tid + i * 256;
            int r  = q >> 3;
            int c4 = q & 7;
            int grow = (r >> 5) * Hsz + jt * 32 + (r & 31);
            cp16(&sB[r * LDA + c4 * 8],
                 &g_Wfp16[(size_t)grow * KTOT + kb + c4 * 8]);
        }
        asm volatile("cp.async.commit_group;" ::: "memory");
    };

    constexpr int NIT = KTOT / BK;   // 32
    issueA(0, 0); issueB(0, 0);
    issueA(1, 1); issueB(1, 1);

    int cs = 0;   // consume stage
    int ps = 2;   // prefetch stage

    for (int it = 0; it < NIT; ++it) {
        if (it == NIT - 1)
            asm volatile("cp.async.wait_group 0;" ::: "memory");
        else
            asm volatile("cp.async.wait_group 1;" ::: "memory");
        __syncthreads();

        const __half* as = sm0 + (size_t)cs * 2 * STAGE_HALVES;
        const __half* ws = as + STAGE_HALVES;
        cs = (cs == NSTAGE - 1) ? 0 : cs + 1;

        const bool pf = (it + 2 < NIT);

        #pragma unroll
        for (int kk = 0; kk < BK; kk += 16) {
            wmma::fragment<wmma::matrix_a, 16, 16, 16, __half, wmma::row_major> a_frag[4];
            wmma::fragment<wmma::matrix_b, 16, 16, 16, __half, wmma::col_major> b_frag[2];
            #pragma unroll
            for (int im = 0; im < 4; im++)
                wmma::load_matrix_sync(a_frag[im], as + (wm * 64 + im * 16) * LDA + kk, LDA);
            #pragma unroll
            for (int in = 0; in < 2; in++)
                wmma::load_matrix_sync(b_frag[in], ws + (wn * 32 + in * 16) * LDA + kk, LDA);
            #pragma unroll
            for (int im = 0; im < 4; im++)
                #pragma unroll
                for (int in = 0; in < 2; in++)
                    wmma::mma_sync(c_frag[im][in], a_frag[im], b_frag[in], c_frag[im][in]);

            if (kk == 0 && pf) issueA(it + 2, ps);
            if (kk == 16 && pf) {
                issueB(it + 2, ps);
                ps = (ps == NSTAGE - 1) ? 0 : ps + 1;
            }
        }
    }
    __syncthreads();

    // ── epilogue: exchange gates via smem, apply LSTM nonlinearity ──
    float* G = reinterpret_cast<float*>(smraw);   // [BM][LDG]
    #pragma unroll
    for (int im = 0; im < 4; im++)
        #pragma unroll
        for (int in = 0; in < 2; in++)
            wmma::store_matrix_sync(&G[(wm * 64 + im * 16) * LDG + wn * 32 + in * 16],
                                    c_frag[im][in], LDG, wmma::mem_row_major);
    __syncthreads();

    for (int idx = tid; idx < BM * 32; idx += 256) {
        int m  = idx >> 5;
        int j  = idx & 31;
        int row = mt * BM + m;
        int jg  = jt * 32 + j;

        float gi = G[m * LDG +      j] + b_ih[0 * Hsz + jg] + b_hh[0 * Hsz + jg];
        float gf = G[m * LDG + 32 + j] + b_ih[1 * Hsz + jg] + b_hh[1 * Hsz + jg];
        float gg = G[m * LDG + 64 + j] + b_ih[2 * Hsz + jg] + b_hh[2 * Hsz + jg];
        float go = G[m * LDG + 96 + j] + b_ih[3 * Hsz + jg] + b_hh[3 * Hsz + jg];

        float si = 1.0f / (1.0f + __expf(-gi));
        float sf = 1.0f / (1.0f + __expf(-gf));
        float so = 1.0f / (1.0f + __expf(-go));
        float tg = tanhf(gg);

        float cold = c0[(size_t)row * Hsz + jg];
        float cn = sf * cold + si * tg;
        float hn = so * tanhf(cn);

        out[(size_t)row * Hsz + jg]                     = hn;
        out[(size_t)Bsz * Hsz + (size_t)row * Hsz + jg] = cn;
    }
}

extern "C" void kernel_launch(void* const* d_in, const int* in_sizes, int n_in,
                              void* d_out, int out_size) {
    const float* x    = (const float*)d_in[0];
    const float* h0   = (const float*)d_in[1];
    const float* c0   = (const float*)d_in[2];
    const float* w_ih = (const float*)d_in[3];
    const float* w_hh = (const float*)d_in[4];
    const float* b_ih = (const float*)d_in[5];
    const float* b_hh = (const float*)d_in[6];
    float* out = (float*)d_out;

    cudaFuncSetAttribute(lstm_fp16_kernel,
                         cudaFuncAttributeMaxDynamicSharedMemorySize, SMEM_BYTES);

    convert_kernel<<<4096, 256>>>(x, h0, w_ih, w_hh);

    dim3 grid(Hsz / 32, Bsz / BM);   // (32, 32)
    lstm_fp16_kernel<<<grid, 256, SMEM_BYTES>>>(c0, b_ih, b_hh, out);
}

// round 11
// speedup vs baseline: 1.5200x; 1.0714x over previous
#include <cuda_runtime.h>
#include <cuda_fp16.h>
#include <cstdint>
#include <mma.h>
#include <math.h>

using namespace nvcuda;

// gates[4096,4096] = [x|h0] @ [w_ih|w_hh]^T, then LSTM nonlinearity.
constexpr int Bsz  = 4096;
constexpr int Hsz  = 1024;
constexpr int KTOT = 2048;

// CTA 128x128 (8 warps, warp tile 64x32 wmma), BK=64, 3-stage cp.async.
constexpr int BM = 128;
constexpr int BK = 64;
constexpr int NSTAGE = 3;
constexpr int LDA = 72;          // halves; 144B rows, LDSM conflict-free
constexpr int LDG = 132;         // epilogue gate-tile stride (floats)

constexpr int STAGE_HALVES = BM * LDA;                       // 9216 per matrix
constexpr int STAGE_BYTES  = 2 * STAGE_HALVES * 2;           // 36864 (A+B)
constexpr int SMEM_BYTES   = NSTAGE * STAGE_BYTES;           // 110592

__device__ __half g_Afp16[(size_t)Bsz * KTOT];
__device__ __half g_Wfp16[(size_t)(4 * Hsz) * KTOT];

// ── convert kernel: fuse + downconvert to fp16 ──────────────────────────────
__global__ void __launch_bounds__(256)
convert_kernel(const float* __restrict__ x,
               const float* __restrict__ h0,
               const float* __restrict__ w_ih,
               const float* __restrict__ w_hh)
{
    const size_t t = (size_t)blockIdx.x * 256 + threadIdx.x;
    const size_t row = t >> 8;
    const size_t ck  = (t & 255) * 8;

    const float* asrc = (ck < 1024) ? (x    + ck) : (h0   + ck - 1024);
    const float* wsrc = (ck < 1024) ? (w_ih + ck) : (w_hh + ck - 1024);

    float4 a0 = *reinterpret_cast<const float4*>(asrc + row * 1024);
    float4 a1 = *reinterpret_cast<const float4*>(asrc + row * 1024 + 4);
    float4 w0 = *reinterpret_cast<const float4*>(wsrc + row * 1024);
    float4 w1 = *reinterpret_cast<const float4*>(wsrc + row * 1024 + 4);

    __half2 ha[4] = {
        __float22half2_rn(make_float2(a0.x, a0.y)),
        __float22half2_rn(make_float2(a0.z, a0.w)),
        __float22half2_rn(make_float2(a1.x, a1.y)),
        __float22half2_rn(make_float2(a1.z, a1.w))};
    __half2 hw[4] = {
        __float22half2_rn(make_float2(w0.x, w0.y)),
        __float22half2_rn(make_float2(w0.z, w0.w)),
        __float22half2_rn(make_float2(w1.x, w1.y)),
        __float22half2_rn(make_float2(w1.z, w1.w))};

    *reinterpret_cast<uint4*>(&g_Afp16[row * KTOT + ck]) = *reinterpret_cast<uint4*>(ha);
    *reinterpret_cast<uint4*>(&g_Wfp16[row * KTOT + ck]) = *reinterpret_cast<uint4*>(hw);
}

__device__ __forceinline__ void cp16(void* s, const void* g) {
    unsigned int sa = (unsigned int)__cvta_generic_to_shared(s);
    asm volatile("cp.async.cg.shared.global [%0], [%1], 16;"
                 :: "r"(sa), "l"(g) : "memory");
}

// ── fused GEMM + LSTM kernel ────────────────────────────────────────────────
__global__ void __launch_bounds__(256, 2)
lstm_fp16_kernel(const float* __restrict__ c0,
                 const float* __restrict__ b_ih,
                 const float* __restrict__ b_hh,
                 float* __restrict__ out)
{
    extern __shared__ __align__(16) char smraw[];
    __half* const sm0 = reinterpret_cast<__half*>(smraw);

    const int jt  = blockIdx.x;      // 32 hidden cols per CTA
    const int mt  = blockIdx.y;      // 128 batch rows per CTA
    const int tid = threadIdx.x;
    const int warp = tid >> 5;
    const int wm = warp >> 2;        // 0..1 -> 64 M rows
    const int wn = warp & 3;         // 0..3 -> gate, 32 N cols

    const int aRow0 = mt * BM;

    // per-thread loader geometry: q = tid + i*256 -> r = (tid>>3) + 32i, c4 = tid&7
    const int rA0 = tid >> 3;            // base row (i=0)
    const int c4  = tid & 7;             // 16B column
    // A: global row aRow0 + rA0 + 32i ; delta per i = 32*KTOT halves
    const __half* gA = g_Afp16 + (size_t)(aRow0 + rA0) * KTOT + c4 * 8;
    // B: grow = (rA0>>5)*Hsz + jt*32 + (rA0&31), delta per i = 1024*KTOT halves
    const __half* gB = g_Wfp16 +
        (size_t)((rA0 >> 5) * Hsz + jt * 32 + (rA0 & 31)) * KTOT + c4 * 8;
    // smem per-thread offset within a stage matrix (halves)
    const int smoff = rA0 * LDA + c4 * 8;

    wmma::fragment<wmma::accumulator, 16, 16, 16, float> c_frag[4][2];
    #pragma unroll
    for (int a = 0; a < 4; a++)
        #pragma unroll
        for (int b = 0; b < 2; b++)
            wmma::fill_fragment(c_frag[a][b], 0.0f);

    // stateful loaders: pointers advance BK halves per call; commit in issueB
    auto issueA = [&](int s) {
        __half* sA = sm0 + (size_t)s * 2 * STAGE_HALVES + smoff;
        #pragma unroll
        for (int i = 0; i < 4; i++)
            cp16(sA + i * (32 * LDA), gA + (size_t)i * (32 * KTOT));
        gA += BK;
    };
    auto issueB = [&](int s) {
        __half* sB = sm0 + (size_t)s * 2 * STAGE_HALVES + STAGE_HALVES + smoff;
        #pragma unroll
        for (int i = 0; i < 4; i++)
            cp16(sB + i * (32 * LDA), gB + (size_t)i * (1024 * KTOT));
        gB += BK;
        asm volatile("cp.async.commit_group;" ::: "memory");
    };

    constexpr int NIT = KTOT / BK;   // 32
    issueA(0); issueB(0);
    issueA(1); issueB(1);

    int cs = 0;   // consume stage
    int ps = 2;   // prefetch stage

    for (int it = 0; it < NIT; ++it) {
        if (it == NIT - 1)
            asm volatile("cp.async.wait_group 0;" ::: "memory");
        else
            asm volatile("cp.async.wait_group 1;" ::: "memory");
        __syncthreads();

        const __half* as = sm0 + (size_t)cs * 2 * STAGE_HALVES;
        const __half* ws = as + STAGE_HALVES;
        cs = (cs == NSTAGE - 1) ? 0 : cs + 1;

        const bool pf = (it + 2 < NIT);

        #pragma unroll
        for (int kk = 0; kk < BK; kk += 16) {
            wmma::fragment<wmma::matrix_a, 16, 16, 16, __half, wmma::row_major> a_frag[4];
            wmma::fragment<wmma::matrix_b, 16, 16, 16, __half, wmma::col_major> b_frag[2];
            #pragma unroll
            for (int im = 0; im < 4; im++)
                wmma::load_matrix_sync(a_frag[im], as + (wm * 64 + im * 16) * LDA + kk, LDA);
            #pragma unroll
            for (int in = 0; in < 2; in++)
                wmma::load_matrix_sync(b_frag[in], ws + (wn * 32 + in * 16) * LDA + kk, LDA);
            #pragma unroll
            for (int im = 0; im < 4; im++)
                #pragma unroll
                for (int in = 0; in < 2; in++)
                    wmma::mma_sync(c_frag[im][in], a_frag[im], b_frag[in], c_frag[im][in]);

            if (kk == 16 && pf) issueA(ps);
            if (kk == 48 && pf) {
                issueB(ps);
                ps = (ps == NSTAGE - 1) ? 0 : ps + 1;
            }
        }
    }
    __syncthreads();

    // ── epilogue: exchange gates via smem, apply LSTM nonlinearity ──
    float* G = reinterpret_cast<float*>(smraw);       // [BM][LDG]
    float* bsum = G + BM * LDG;                       // 128 floats (gate*32 + j)
    #pragma unroll
    for (int im = 0; im < 4; im++)
        #pragma unroll
        for (int in = 0; in < 2; in++)
            wmma::store_matrix_sync(&G[(wm * 64 + im * 16) * LDG + wn * 32 + in * 16],
                                    c_frag[im][in], LDG, wmma::mem_row_major);
    if (tid < 128) {
        const int g = tid >> 5;
        const int jg = jt * 32 + (tid & 31);
        bsum[tid] = b_ih[g * Hsz + jg] + b_hh[g * Hsz + jg];
    }
    __syncthreads();

    {
        const int j = tid & 31;                        // constant per thread
        const float bi = bsum[      j];
        const float bf = bsum[ 32 + j];
        const float bg = bsum[ 64 + j];
        const float bo = bsum[ 96 + j];
        const int jg = jt * 32 + j;

        for (int idx = tid; idx < BM * 32; idx += 256) {
            int m  = idx >> 5;
            int row = mt * BM + m;

            float gi = G[m * LDG +      j] + bi;
            float gf = G[m * LDG + 32 + j] + bf;
            float gg = G[m * LDG + 64 + j] + bg;
            float go = G[m * LDG + 96 + j] + bo;

            float si = 1.0f / (1.0f + __expf(-gi));
            float sf = 1.0f / (1.0f + __expf(-gf));
            float so = 1.0f / (1.0f + __expf(-go));
            float tg = tanhf(gg);

            float cold = c0[(size_t)row * Hsz + jg];
            float cn = sf * cold + si * tg;
            float hn = so * tanhf(cn);

            out[(size_t)row * Hsz + jg]                     = hn;
            out[(size_t)Bsz * Hsz + (size_t)row * Hsz + jg] = cn;
        }
    }
}

extern "C" void kernel_launch(void* const* d_in, const int* in_sizes, int n_in,
                              void* d_out, int out_size) {
    const float* x    = (const float*)d_in[0];
    const float* h0   = (const float*)d_in[1];
    const float* c0   = (const float*)d_in[2];
    const float* w_ih = (const float*)d_in[3];
    const float* w_hh = (const float*)d_in[4];
    const float* b_ih = (const float*)d_in[5];
    const float* b_hh = (const float*)d_in[6];
    float* out = (float*)d_out;

    cudaFuncSetAttribute(lstm_fp16_kernel,
                         cudaFuncAttributeMaxDynamicSharedMemorySize, SMEM_BYTES);

    convert_kernel<<<4096, 256>>>(x, h0, w_ih, w_hh);

    dim3 grid(Hsz / 32, Bsz / BM);   // (32, 32)
    lstm_fp16_kernel<<<grid, 256, SMEM_BYTES>>>(c0, b_ih, b_hh, out);
}